// round 10
// baseline (speedup 1.0000x reference)
#include <cuda_runtime.h>
#include <cuda_fp16.h>
#include <math.h>
#include <cstdint>

// Problem constants
#define BB   2
#define KK   8
#define CC   256
#define HW   16384
#define SS   2048
#define SIM_TH 0.95f
#define CAND_TH 0.92f        // SIM_TH minus fp16-accumulation slack
#define EPS_DEN 1e-6f
#define EPS_NRM 1e-12f

// Filter-Gram tiling
#define TM 128
#define TN 128
#define KF 64                 // filter channels
#define NT (SS / TM)          // 16
#define NPAIR ((NT * (NT + 1)) / 2)   // 136
#define GRID2 (BB * NPAIR)    // 272
#define SROW 72               // padded smem row (f16)

// Scratch (no allocation allowed)
__device__ __align__(16) __half g_fh[BB][SS][CC];  // normalized features, f16
__device__ float g_r[BB][SS];                      // tail norm ||f̂[64:]||
__device__ float g_m[BB][KK][SS];
__device__ float g_num;
__device__ float g_den;
__device__ unsigned g_done;

// ---------------------------------------------------------------------------
// Kernel 1: gather + normalize (f16 out) + tail-norm r + mask sigmoid + init.
// One warp per sample. grid 512 x 256.
// ---------------------------------------------------------------------------
__global__ void gather_kernel(const float* __restrict__ masks,
                              const float* __restrict__ feats,
                              const int*   __restrict__ indices)
{
    const int tid  = threadIdx.x;
    const int lane = tid & 31;
    const int gtid = blockIdx.x * blockDim.x + tid;

    if (gtid == 0) { g_num = 0.0f; g_den = 0.0f; g_done = 0u; }

    // mask gather: 32768 entries, 64 per block
    if (tid < 64) {
        int e = blockIdx.x * 64 + tid;
        int b = e / (KK * SS);
        int r = e % (KK * SS);
        int k = r / SS;
        int s = r % SS;
        int hw = indices[b * SS + s];
        float x = masks[(b * KK + k) * HW + hw];
        g_m[b][k][s] = 1.0f / (1.0f + expf(-x));
    }

    const int warp = gtid >> 5;          // 0..4095
    const int b = warp >> 11;
    const int s = warp & 2047;
    const int hw = indices[b * SS + s];

    float v[8];
    float ss = 0.0f;
#pragma unroll
    for (int u = 0; u < 8; u++) {
        int c = u * 32 + lane;
        float x = feats[((size_t)(b * CC + c)) * HW + hw];
        v[u] = x;
        ss += x * x;
    }
    // head (c<64) sum of squares: u = 0,1 cover c = 0..63
    float ps = v[0] * v[0] + v[1] * v[1];
#pragma unroll
    for (int off = 16; off > 0; off >>= 1) {
        ss += __shfl_xor_sync(0xFFFFFFFFu, ss, off);
        ps += __shfl_xor_sync(0xFFFFFFFFu, ps, off);
    }

    float inv = 1.0f / fmaxf(sqrtf(ss), EPS_NRM);
    if (lane == 0) {
        float pn = ps * inv * inv;               // ||f̂[0:64]||^2
        g_r[b][s] = sqrtf(fmaxf(1.0f - pn, 0.0f));
    }
#pragma unroll
    for (int u = 0; u < 8; u++)
        g_fh[b][s][u * 32 + lane] = __float2half(v[u] * inv);
}

// ---------------------------------------------------------------------------
// Kernel 2: 64-channel filter Gram (f16 mma, fp16 acc) + Cauchy-Schwarz
// candidate filter + exact fp32 refinement + fused affinity + final scalar.
// 256 threads, 8 warps (2x4 grid, warp tile 64x32). Static smem ~46 KB.
// ---------------------------------------------------------------------------
__global__ __launch_bounds__(256)
void gram_affinity_kernel(float* __restrict__ out)
{
    __shared__ __half As[TM][SROW];      // 18.4 KB
    __shared__ __half Bs[TN][SROW];      // 18.4 KB
    __shared__ float Ms[KK][TM];
    __shared__ float Mt[KK][TN];
    __shared__ float Sr[TM];
    __shared__ float Sc[TN];
    __shared__ float red[16];

    const int tid = threadIdx.x;
    const int b = blockIdx.x / NPAIR;
    int p = blockIdx.x % NPAIR;

    int j = 0;
    while (((j + 1) * (j + 2)) / 2 <= p) j++;
    int i = p - (j * (j + 1)) / 2;

    const int s0 = i * TM;
    const int t0 = j * TN;
    const float w = (i == j) ? 1.0f : 2.0f;

    const int lane = tid & 31;
    const int wid  = tid >> 5;
    const int wm   = wid & 1;
    const int wn   = wid >> 1;

    // stage the 64-channel tiles: 1024 uint4 per matrix, 4 per thread
#pragma unroll
    for (int it = 0; it < 4; it++) {
        int idx = tid + it * 256;
        int row = idx >> 3;
        int ch  = (idx & 7) * 8;
        *(uint4*)&As[row][ch] = *(const uint4*)&g_fh[b][s0 + row][ch];
        *(uint4*)&Bs[row][ch] = *(const uint4*)&g_fh[b][t0 + row][ch];
    }
    // m tiles + tail norms
#pragma unroll
    for (int it = 0; it < 4; it++) {
        int q = tid + it * 256;
        int k = q >> 7;
        int r = q & 127;
        Ms[k][r] = g_m[b][k][s0 + r];
        Mt[k][r] = g_m[b][k][t0 + r];
    }
    if (tid < 128)      Sr[tid]       = g_r[b][s0 + tid];
    else                Sc[tid - 128] = g_r[b][t0 + tid - 128];
    __syncthreads();

    uint32_t acc[4][4][2];
#pragma unroll
    for (int im = 0; im < 4; im++)
#pragma unroll
        for (int in = 0; in < 4; in++) { acc[im][in][0] = 0u; acc[im][in][1] = 0u; }

    const int a_r   = lane & 15;
    const int a_sel = (lane >> 4) << 3;
    const int b_r   = (lane & 7) + ((lane >> 4) << 3);
    const int b_sel = ((lane >> 3) & 1) << 3;

#pragma unroll
    for (int kk = 0; kk < KF; kk += 16) {
        unsigned af[4][4];
#pragma unroll
        for (int im = 0; im < 4; im++) {
            unsigned addr = (unsigned)__cvta_generic_to_shared(
                &As[wm * 64 + im * 16 + a_r][kk + a_sel]);
            asm volatile(
                "ldmatrix.sync.aligned.m8n8.x4.shared.b16 {%0,%1,%2,%3}, [%4];"
                : "=r"(af[im][0]), "=r"(af[im][1]), "=r"(af[im][2]), "=r"(af[im][3])
                : "r"(addr));
        }
        unsigned bq[2][4];
#pragma unroll
        for (int q = 0; q < 2; q++) {
            unsigned addr = (unsigned)__cvta_generic_to_shared(
                &Bs[wn * 32 + q * 16 + b_r][kk + b_sel]);
            asm volatile(
                "ldmatrix.sync.aligned.m8n8.x4.shared.b16 {%0,%1,%2,%3}, [%4];"
                : "=r"(bq[q][0]), "=r"(bq[q][1]), "=r"(bq[q][2]), "=r"(bq[q][3])
                : "r"(addr));
        }
#pragma unroll
        for (int im = 0; im < 4; im++) {
#pragma unroll
            for (int in = 0; in < 4; in++) {
                unsigned b0 = bq[in >> 1][(in & 1) * 2];
                unsigned b1 = bq[in >> 1][(in & 1) * 2 + 1];
                asm volatile(
                    "mma.sync.aligned.m16n8k16.row.col.f16.f16.f16.f16 "
                    "{%0,%1}, {%2,%3,%4,%5}, {%6,%7}, {%0,%1};"
                    : "+r"(acc[im][in][0]), "+r"(acc[im][in][1])
                    : "r"(af[im][0]), "r"(af[im][1]), "r"(af[im][2]), "r"(af[im][3]),
                      "r"(b0), "r"(b1));
            }
        }
    }

    // epilogue: Cauchy-Schwarz filter, exact refine for candidates
    const int gr = lane >> 2;
    const int gc = (lane & 3) * 2;

    float numL = 0.0f, denL = 0.0f;
#pragma unroll
    for (int im = 0; im < 4; im++) {
#pragma unroll
        for (int in = 0; in < 4; in++) {
#pragma unroll
            for (int r = 0; r < 4; r++) {
                __half2 h2 = *(__half2*)&acc[im][in][r >> 1];
                float pdot = (r & 1) ? __high2float(h2) : __low2float(h2);
                int row = wm * 64 + im * 16 + gr + ((r >> 1) << 3);
                int col = wn * 32 + in * 8 + gc + (r & 1);
                // candidate iff head dot + tail bound can reach threshold
                if (pdot + Sr[row] * Sc[col] > CAND_TH) {
                    // exact fp32 dot over all 256 channels
                    const uint4* pa = (const uint4*)&g_fh[b][s0 + row][0];
                    const uint4* pb = (const uint4*)&g_fh[b][t0 + col][0];
                    float dot = 0.0f;
                    for (int q = 0; q < 32; q++) {
                        uint4 ua = pa[q], ub = pb[q];
                        const __half2* ha = (const __half2*)&ua;
                        const __half2* hb = (const __half2*)&ub;
#pragma unroll
                        for (int t = 0; t < 4; t++) {
                            float2 a2 = __half22float2(ha[t]);
                            float2 c2 = __half22float2(hb[t]);
                            dot += a2.x * c2.x + a2.y * c2.y;
                        }
                    }
                    if (dot > SIM_TH) {
                        denL += 1.0f;
                        float d = 0.0f;
#pragma unroll
                        for (int k = 0; k < KK; k++)
                            d += fabsf(Ms[k][row] - Mt[k][col]);
                        numL += d;
                    }
                }
            }
        }
    }
    numL *= w;
    denL *= w;

#pragma unroll
    for (int off = 16; off > 0; off >>= 1) {
        numL += __shfl_xor_sync(0xFFFFFFFFu, numL, off);
        denL += __shfl_xor_sync(0xFFFFFFFFu, denL, off);
    }
    if (lane == 0) { red[wid] = numL; red[8 + wid] = denL; }
    __syncthreads();
    if (tid == 0) {
        float n = 0.0f, d = 0.0f;
#pragma unroll
        for (int q = 0; q < 8; q++) { n += red[q]; d += red[8 + q]; }
        atomicAdd(&g_num, n);
        atomicAdd(&g_den, d);
        __threadfence();
        unsigned t = atomicAdd(&g_done, 1u);
        if (t == GRID2 - 1) {
            out[0] = g_num / (g_den + EPS_DEN);
        }
    }
}

extern "C" void kernel_launch(void* const* d_in, const int* in_sizes, int n_in,
                              void* d_out, int out_size)
{
    const float* masks   = (const float*)d_in[0];
    const float* feats   = (const float*)d_in[1];
    const int*   indices = (const int*)d_in[2];
    float* out = (float*)d_out;

    gather_kernel<<<512, 256>>>(masks, feats, indices);
    gram_affinity_kernel<<<GRID2, 256>>>(out);
}

// round 11
// speedup vs baseline: 1.9646x; 1.9646x over previous
#include <cuda_runtime.h>
#include <cuda_fp16.h>
#include <math.h>
#include <cstdint>

// Problem constants
#define BB   2
#define KK   8
#define CC   256
#define HW   16384
#define SS   2048
#define SIM_TH 0.95f
#define EPS_DEN 1e-6f
#define EPS_NRM 1e-12f

// Gram tiling
#define TM 128
#define TN 128
#define KC 64
#define NT (SS / TM)                  // 16
#define NPAIR ((NT * (NT + 1)) / 2)   // 136
#define GRID2 (BB * NPAIR)            // 272
#define SROW 72                       // padded smem row (f16)

// Scratch (no allocation allowed). All zero-initialized at load; the last
// block of every run resets them so each graph replay starts from zeros.
__device__ __align__(16) __half g_fh[BB][SS][CC];
__device__ float g_m[BB][KK][SS];
__device__ int   g_scnt[32];          // per-(batch,strip) completion counters
__device__ float g_num;
__device__ float g_den;
__device__ unsigned g_done;

__device__ __forceinline__ int ld_acq(const int* p) {
    int v;
    asm volatile("ld.acquire.gpu.global.b32 %0, [%1];" : "=r"(v) : "l"(p) : "memory");
    return v;
}

// ---------------------------------------------------------------------------
// Single fused kernel: 272 blocks x 256 threads (single wave: 2 blocks/SM).
// Blocks 0..255: gather 16 samples (+ masks), flag strip. All blocks: wait
// for their tile's two strips, then tensor-core Gram + fused affinity.
// ---------------------------------------------------------------------------
__global__ __launch_bounds__(256)
void fused_kernel(const float* __restrict__ masks,
                  const float* __restrict__ feats,
                  const int*   __restrict__ indices,
                  float* __restrict__ out)
{
    __shared__ __half As[TM][SROW];      // 18.4 KB
    __shared__ __half Bs[TN][SROW];      // 18.4 KB
    __shared__ float Ms[KK][TM];
    __shared__ float Mt[KK][TN];
    __shared__ float red[16];

    const int tid  = threadIdx.x;
    const int lane = tid & 31;
    const int wid  = tid >> 5;
    const int bid  = blockIdx.x;

    // ---------------- Phase 1: gather (blocks 0..255) ----------------
    if (bid < 256) {
        // mask gather: 16 samples x 8 masks = 128 entries
        if (tid < 128) {
            int q = tid >> 3;
            int k = tid & 7;
            int g = bid * 16 + q;
            int gb = g >> 11;
            int gs = g & 2047;
            int hw = indices[gb * SS + gs];
            float x = masks[(gb * KK + k) * HW + hw];
            g_m[gb][k][gs] = 1.0f / (1.0f + expf(-x));
        }

        // features: each warp handles 2 samples, interleaved for MLP
        const int g0 = bid * 16 + wid * 2;
        const int gb = g0 >> 11;
        const int gs0 = g0 & 2047;
        const int gs1 = gs0 + 1;
        const int hw0 = indices[gb * SS + gs0];
        const int hw1 = indices[gb * SS + gs1];

        float v0[8], v1[8];
        float q0 = 0.0f, q1 = 0.0f;
#pragma unroll
        for (int u = 0; u < 8; u++) {
            int c = u * 32 + lane;
            size_t base = ((size_t)(gb * CC + c)) * HW;
            float a = feats[base + hw0];
            float c1 = feats[base + hw1];
            v0[u] = a;  q0 += a * a;
            v1[u] = c1; q1 += c1 * c1;
        }
#pragma unroll
        for (int off = 16; off > 0; off >>= 1) {
            q0 += __shfl_xor_sync(0xFFFFFFFFu, q0, off);
            q1 += __shfl_xor_sync(0xFFFFFFFFu, q1, off);
        }
        float inv0 = 1.0f / fmaxf(sqrtf(q0), EPS_NRM);
        float inv1 = 1.0f / fmaxf(sqrtf(q1), EPS_NRM);
#pragma unroll
        for (int u = 0; u < 8; u++) {
            int c = u * 32 + lane;
            g_fh[gb][gs0][c] = __float2half(v0[u] * inv0);
            g_fh[gb][gs1][c] = __float2half(v1[u] * inv1);
        }

        __threadfence();
        __syncthreads();
        if (tid == 0) atomicAdd(&g_scnt[bid >> 3], 1);   // 8 blocks per strip
    }

    // ---------------- Phase 2: Gram tile ----------------
    const int b = bid / NPAIR;
    int p = bid % NPAIR;
    int j = 0;
    while (((j + 1) * (j + 2)) / 2 <= p) j++;
    int i = p - (j * (j + 1)) / 2;

    const int s0 = i * TM;
    const int t0 = j * TN;
    const float w = (i == j) ? 1.0f : 2.0f;

    // wait for both strips to be fully gathered
    if (tid == 0) {
        const int* ci = &g_scnt[b * 16 + i];
        const int* cj = &g_scnt[b * 16 + j];
        while (ld_acq(ci) < 8) __nanosleep(128);
        while (ld_acq(cj) < 8) __nanosleep(128);
    }
    __syncthreads();

    // m tiles
#pragma unroll
    for (int it = 0; it < 4; it++) {
        int q = tid + it * 256;
        int k = q >> 7;
        int r = q & 127;
        Ms[k][r] = g_m[b][k][s0 + r];
        Mt[k][r] = g_m[b][k][t0 + r];
    }

    const int wm = wid & 1;
    const int wn = wid >> 1;

    uint32_t acc[4][4][2];
#pragma unroll
    for (int im = 0; im < 4; im++)
#pragma unroll
        for (int in = 0; in < 4; in++) { acc[im][in][0] = 0u; acc[im][in][1] = 0u; }

    const int a_r   = lane & 15;
    const int a_sel = (lane >> 4) << 3;
    const int b_r   = (lane & 7) + ((lane >> 4) << 3);
    const int b_sel = ((lane >> 3) & 1) << 3;

#pragma unroll 1
    for (int ck = 0; ck < 4; ck++) {
        const int kc = ck * KC;
        __syncthreads();
        // stage 128 rows x 64 f16 per matrix: 1024 int4, 4 per thread
#pragma unroll
        for (int it = 0; it < 4; it++) {
            int idx = tid + it * 256;
            int row = idx >> 3;
            int ch  = (idx & 7) * 8;
            *(uint4*)&As[row][ch] = *(const uint4*)&g_fh[b][s0 + row][kc + ch];
            *(uint4*)&Bs[row][ch] = *(const uint4*)&g_fh[b][t0 + row][kc + ch];
        }
        __syncthreads();

#pragma unroll
        for (int kk = 0; kk < KC; kk += 16) {
            unsigned af[4][4];
#pragma unroll
            for (int im = 0; im < 4; im++) {
                unsigned addr = (unsigned)__cvta_generic_to_shared(
                    &As[wm * 64 + im * 16 + a_r][kk + a_sel]);
                asm volatile(
                    "ldmatrix.sync.aligned.m8n8.x4.shared.b16 {%0,%1,%2,%3}, [%4];"
                    : "=r"(af[im][0]), "=r"(af[im][1]), "=r"(af[im][2]), "=r"(af[im][3])
                    : "r"(addr));
            }
            unsigned bq[2][4];
#pragma unroll
            for (int q = 0; q < 2; q++) {
                unsigned addr = (unsigned)__cvta_generic_to_shared(
                    &Bs[wn * 32 + q * 16 + b_r][kk + b_sel]);
                asm volatile(
                    "ldmatrix.sync.aligned.m8n8.x4.shared.b16 {%0,%1,%2,%3}, [%4];"
                    : "=r"(bq[q][0]), "=r"(bq[q][1]), "=r"(bq[q][2]), "=r"(bq[q][3])
                    : "r"(addr));
            }
#pragma unroll
            for (int im = 0; im < 4; im++) {
#pragma unroll
                for (int in = 0; in < 4; in++) {
                    unsigned b0 = bq[in >> 1][(in & 1) * 2];
                    unsigned b1 = bq[in >> 1][(in & 1) * 2 + 1];
                    asm volatile(
                        "mma.sync.aligned.m16n8k16.row.col.f16.f16.f16.f16 "
                        "{%0,%1}, {%2,%3,%4,%5}, {%6,%7}, {%0,%1};"
                        : "+r"(acc[im][in][0]), "+r"(acc[im][in][1])
                        : "r"(af[im][0]), "r"(af[im][1]), "r"(af[im][2]), "r"(af[im][3]),
                          "r"(b0), "r"(b1));
                }
            }
        }
    }

    // fused affinity epilogue (threshold branch rarely taken)
    const int gr = lane >> 2;
    const int gc = (lane & 3) * 2;
    float numL = 0.0f, denL = 0.0f;
#pragma unroll
    for (int im = 0; im < 4; im++) {
#pragma unroll
        for (int in = 0; in < 4; in++) {
#pragma unroll
            for (int r = 0; r < 4; r++) {
                __half2 h2 = *(__half2*)&acc[im][in][r >> 1];
                float v = (r & 1) ? __high2float(h2) : __low2float(h2);
                if (v > SIM_TH) {
                    int row = wm * 64 + im * 16 + gr + ((r >> 1) << 3);
                    int col = wn * 32 + in * 8 + gc + (r & 1);
                    denL += 1.0f;
                    float d = 0.0f;
#pragma unroll
                    for (int k = 0; k < KK; k++)
                        d += fabsf(Ms[k][row] - Mt[k][col]);
                    numL += d;
                }
            }
        }
    }
    numL *= w;
    denL *= w;

#pragma unroll
    for (int off = 16; off > 0; off >>= 1) {
        numL += __shfl_xor_sync(0xFFFFFFFFu, numL, off);
        denL += __shfl_xor_sync(0xFFFFFFFFu, denL, off);
    }
    if (lane == 0) { red[wid] = numL; red[8 + wid] = denL; }
    __syncthreads();
    if (tid == 0) {
        float n = 0.0f, d = 0.0f;
#pragma unroll
        for (int q = 0; q < 8; q++) { n += red[q]; d += red[8 + q]; }
        atomicAdd(&g_num, n);
        atomicAdd(&g_den, d);
        __threadfence();
        unsigned t = atomicAdd(&g_done, 1u);
        if (t == GRID2 - 1) {
            __threadfence();
            out[0] = g_num / (g_den + EPS_DEN);
            // reset state for the next graph replay
            g_num = 0.0f;
            g_den = 0.0f;
            g_done = 0u;
#pragma unroll
            for (int q = 0; q < 32; q++) g_scnt[q] = 0;
        }
    }
}

extern "C" void kernel_launch(void* const* d_in, const int* in_sizes, int n_in,
                              void* d_out, int out_size)
{
    const float* masks   = (const float*)d_in[0];
    const float* feats   = (const float*)d_in[1];
    const int*   indices = (const int*)d_in[2];
    float* out = (float*)d_out;

    fused_kernel<<<GRID2, 256>>>(masks, feats, indices, out);
}

// round 13
// speedup vs baseline: 1.9872x; 1.0115x over previous
#include <cuda_runtime.h>
#include <cuda_fp16.h>
#include <math.h>
#include <cstdint>

// Problem constants
#define BB   2
#define KK   8
#define CC   256
#define HW   16384
#define SS   2048
#define SIM_TH 0.95f
#define EPS_DEN 1e-6f
#define EPS_NRM 1e-12f

// Gram tiling
#define TM 128
#define TN 128
#define KC 64
#define NT (SS / TM)                  // 16
#define NPAIR ((NT * (NT + 1)) / 2)   // 136
#define GRID2 (BB * NPAIR)            // 272
#define SROW 72                       // padded smem row (f16)

// Scratch (no allocation allowed); reset by last block each run.
__device__ __align__(16) __half g_fh[BB][SS][CC];
__device__ float g_m[BB][KK][SS];
__device__ int   g_scnt[32];
__device__ float g_num;
__device__ float g_den;
__device__ unsigned g_done;

__device__ __forceinline__ int ld_acq(const int* p) {
    int v;
    asm volatile("ld.acquire.gpu.global.b32 %0, [%1];" : "=r"(v) : "l"(p) : "memory");
    return v;
}

// ---------------------------------------------------------------------------
// Fused kernel: 272 blocks x 512 threads (2 CTAs/SM -> all resident).
// Phase 1 (blocks 0..255): one warp per sample, 16 samples/block + masks.
// Phase 2 (all blocks): spin on strip flags, then 128x128 Gram tile with
// 16 warps (4x4 grid, warp tile 32x32) + fused affinity + final scalar.
// ---------------------------------------------------------------------------
__global__ __launch_bounds__(512, 2)
void fused_kernel(const float* __restrict__ masks,
                  const float* __restrict__ feats,
                  const int*   __restrict__ indices,
                  float* __restrict__ out)
{
    __shared__ __half As[TM][SROW];      // 18.4 KB
    __shared__ __half Bs[TN][SROW];      // 18.4 KB
    __shared__ float Ms[KK][TM];
    __shared__ float Mt[KK][TN];
    __shared__ float red[32];

    const int tid  = threadIdx.x;
    const int lane = tid & 31;
    const int wid  = tid >> 5;           // 0..15
    const int bid  = blockIdx.x;

    // ---------------- Phase 1: gather ----------------
    const int gwarp = bid * 16 + wid;
    if (gwarp < BB * SS) {
        const int gb = gwarp >> 11;
        const int gs = gwarp & 2047;
        const int hw = indices[gb * SS + gs];

        float v[8];
        float q = 0.0f;
#pragma unroll
        for (int u = 0; u < 8; u++) {
            int c = u * 32 + lane;
            float x = feats[((size_t)(gb * CC + c)) * HW + hw];
            v[u] = x;
            q += x * x;
        }
#pragma unroll
        for (int off = 16; off > 0; off >>= 1)
            q += __shfl_xor_sync(0xFFFFFFFFu, q, off);
        float inv = 1.0f / fmaxf(sqrtf(q), EPS_NRM);
#pragma unroll
        for (int u = 0; u < 8; u++)
            g_fh[gb][gs][u * 32 + lane] = __float2half(v[u] * inv);
    }
    if (bid < 256 && tid < 128) {
        // mask gather: 16 samples x 8 masks per block
        int q = tid >> 3;
        int k = tid & 7;
        int g = bid * 16 + q;
        int gb = g >> 11;
        int gs = g & 2047;
        int hw = indices[gb * SS + gs];
        float x = masks[(gb * KK + k) * HW + hw];
        g_m[gb][k][gs] = 1.0f / (1.0f + expf(-x));
    }
    if (bid < 256) {
        __threadfence();
        __syncthreads();
        if (tid == 0) atomicAdd(&g_scnt[bid >> 3], 1);   // 8 blocks per strip
    }

    // ---------------- Phase 2: Gram tile ----------------
    const int b = bid / NPAIR;
    int p = bid % NPAIR;
    int j = 0;
    while (((j + 1) * (j + 2)) / 2 <= p) j++;
    int i = p - (j * (j + 1)) / 2;

    const int s0 = i * TM;
    const int t0 = j * TN;
    const float w = (i == j) ? 1.0f : 2.0f;

    if (tid == 0) {
        const int* ci = &g_scnt[b * 16 + i];
        const int* cj = &g_scnt[b * 16 + j];
        while (ld_acq(ci) < 8) __nanosleep(128);
        while (ld_acq(cj) < 8) __nanosleep(128);
    }
    __syncthreads();

    // m tiles: 2 x 8 x 128 floats = 2048, 512 threads -> 4 each (2 iters x 2 tiles)
#pragma unroll
    for (int it = 0; it < 2; it++) {
        int q = tid + it * 512;          // 0..1023
        int k = q >> 7;                  // 0..7
        int r = q & 127;
        Ms[k][r] = g_m[b][k][s0 + r];
        Mt[k][r] = g_m[b][k][t0 + r];
    }

    const int wm = wid & 3;              // 4 m-strips of 32 rows
    const int wn = wid >> 2;             // 4 n-strips of 32 cols

    uint32_t acc[2][4][2];
#pragma unroll
    for (int im = 0; im < 2; im++)
#pragma unroll
        for (int in = 0; in < 4; in++) { acc[im][in][0] = 0u; acc[im][in][1] = 0u; }

    const int a_r   = lane & 15;
    const int a_sel = (lane >> 4) << 3;
    const int b_r   = (lane & 7) + ((lane >> 4) << 3);
    const int b_sel = ((lane >> 3) & 1) << 3;

#pragma unroll 1
    for (int ck = 0; ck < 4; ck++) {
        const int kc = ck * KC;
        __syncthreads();
        // stage: 1024 int4 per matrix, 2 per thread
#pragma unroll
        for (int it = 0; it < 2; it++) {
            int idx = tid + it * 512;
            int row = idx >> 3;
            int ch  = (idx & 7) * 8;
            *(uint4*)&As[row][ch] = *(const uint4*)&g_fh[b][s0 + row][kc + ch];
            *(uint4*)&Bs[row][ch] = *(const uint4*)&g_fh[b][t0 + row][kc + ch];
        }
        __syncthreads();

#pragma unroll
        for (int kk = 0; kk < KC; kk += 16) {
            unsigned af[2][4];
#pragma unroll
            for (int im = 0; im < 2; im++) {
                unsigned addr = (unsigned)__cvta_generic_to_shared(
                    &As[wm * 32 + im * 16 + a_r][kk + a_sel]);
                asm volatile(
                    "ldmatrix.sync.aligned.m8n8.x4.shared.b16 {%0,%1,%2,%3}, [%4];"
                    : "=r"(af[im][0]), "=r"(af[im][1]), "=r"(af[im][2]), "=r"(af[im][3])
                    : "r"(addr));
            }
            unsigned bq[2][4];
#pragma unroll
            for (int q = 0; q < 2; q++) {
                unsigned addr = (unsigned)__cvta_generic_to_shared(
                    &Bs[wn * 32 + q * 16 + b_r][kk + b_sel]);
                asm volatile(
                    "ldmatrix.sync.aligned.m8n8.x4.shared.b16 {%0,%1,%2,%3}, [%4];"
                    : "=r"(bq[q][0]), "=r"(bq[q][1]), "=r"(bq[q][2]), "=r"(bq[q][3])
                    : "r"(addr));
            }
#pragma unroll
            for (int im = 0; im < 2; im++) {
#pragma unroll
                for (int in = 0; in < 4; in++) {
                    unsigned b0 = bq[in >> 1][(in & 1) * 2];
                    unsigned b1 = bq[in >> 1][(in & 1) * 2 + 1];
                    asm volatile(
                        "mma.sync.aligned.m16n8k16.row.col.f16.f16.f16.f16 "
                        "{%0,%1}, {%2,%3,%4,%5}, {%6,%7}, {%0,%1};"
                        : "+r"(acc[im][in][0]), "+r"(acc[im][in][1])
                        : "r"(af[im][0]), "r"(af[im][1]), "r"(af[im][2]), "r"(af[im][3]),
                          "r"(b0), "r"(b1));
                }
            }
        }
    }

    // fused affinity epilogue
    const int gr = lane >> 2;
    const int gc = (lane & 3) * 2;
    float numL = 0.0f, denL = 0.0f;
#pragma unroll
    for (int im = 0; im < 2; im++) {
#pragma unroll
        for (int in = 0; in < 4; in++) {
#pragma unroll
            for (int r = 0; r < 4; r++) {
                __half2 h2 = *(__half2*)&acc[im][in][r >> 1];
                float v = (r & 1) ? __high2float(h2) : __low2float(h2);
                if (v > SIM_TH) {
                    int row = wm * 32 + im * 16 + gr + ((r >> 1) << 3);
                    int col = wn * 32 + in * 8 + gc + (r & 1);
                    denL += 1.0f;
                    float d = 0.0f;
#pragma unroll
                    for (int k = 0; k < KK; k++)
                        d += fabsf(Ms[k][row] - Mt[k][col]);
                    numL += d;
                }
            }
        }
    }
    numL *= w;
    denL *= w;

#pragma unroll
    for (int off = 16; off > 0; off >>= 1) {
        numL += __shfl_xor_sync(0xFFFFFFFFu, numL, off);
        denL += __shfl_xor_sync(0xFFFFFFFFu, denL, off);
    }
    if (lane == 0) { red[wid] = numL; red[16 + wid] = denL; }
    __syncthreads();
    if (tid == 0) {
        float n = 0.0f, d = 0.0f;
#pragma unroll
        for (int q = 0; q < 16; q++) { n += red[q]; d += red[16 + q]; }
        atomicAdd(&g_num, n);
        atomicAdd(&g_den, d);
        __threadfence();
        unsigned t = atomicAdd(&g_done, 1u);
        if (t == GRID2 - 1) {
            __threadfence();
            out[0] = g_num / (g_den + EPS_DEN);
            g_num = 0.0f;
            g_den = 0.0f;
            g_done = 0u;
#pragma unroll
            for (int q = 0; q < 32; q++) g_scnt[q] = 0;
        }
    }
}

extern "C" void kernel_launch(void* const* d_in, const int* in_sizes, int n_in,
                              void* d_out, int out_size)
{
    const float* masks   = (const float*)d_in[0];
    const float* feats   = (const float*)d_in[1];
    const int*   indices = (const int*)d_in[2];
    float* out = (float*)d_out;

    fused_kernel<<<GRID2, 512>>>(masks, feats, indices, out);
}